// round 6
// baseline (speedup 1.0000x reference)
#include <cuda_runtime.h>
#include <cstdint>
#include <math.h>

#define TLEN 4096
#define HDIM 256
#define SENT 0x7fc00000u

// ---------------- scratch (static device arrays; no allocation) ----------------
__device__ float g_xsf[TLEN * 1024];   // 16 MB  input-proj forward (reused per layer)
__device__ float g_xsb[TLEN * 1024];   // 16 MB  input-proj backward
__device__ float g_h1 [TLEN * 512];    // 8 MB   layer0 output [hf | hb]
__device__ float g_h2 [TLEN * 512];    // 8 MB   layer1 output
__device__ float g_z  [TLEN * 256];    // 4 MB   fc1 output
__device__ float g_e  [TLEN * 256];    // 4 MB   fc2 output
__device__ float g_nrm[TLEN];          // row norms of e

// ---------------- generic 128x128 SGEMM: C = A(MxK) * B(NxK)^T (+epilogue) ------
// mode 0: C += bias ; mode 1: relu(C + bias) ; mode 2: cosine-distance epilogue
__global__ __launch_bounds__(256, 1)
void gemm_k(const float* __restrict__ A, const float* __restrict__ B,
            const float* __restrict__ bias, const float* __restrict__ nrm,
            float* __restrict__ C, int M, int N, int K, int mode)
{
    __shared__ float As[16][128];
    __shared__ float Bs[16][128];

    const int tid = threadIdx.x;
    const int bm = blockIdx.y << 7;
    const int bn = blockIdx.x << 7;
    const int tx = tid & 15;
    const int ty = tid >> 4;
    const int lr = tid >> 2;
    const int lc = (tid & 3) << 2;

    const float* Ap = A + (size_t)(bm + lr) * K + lc;
    const float* Bp = B + (size_t)(bn + lr) * K + lc;

    float acc[8][8];
#pragma unroll
    for (int i = 0; i < 8; i++)
#pragma unroll
        for (int j = 0; j < 8; j++) acc[i][j] = 0.f;

    for (int k0 = 0; k0 < K; k0 += 16) {
        float4 a0 = *(const float4*)(Ap + k0);
        float4 a1 = *(const float4*)(Ap + (size_t)64 * K + k0);
        float4 b0 = *(const float4*)(Bp + k0);
        float4 b1 = *(const float4*)(Bp + (size_t)64 * K + k0);
        __syncthreads();
        As[lc + 0][lr] = a0.x; As[lc + 1][lr] = a0.y; As[lc + 2][lr] = a0.z; As[lc + 3][lr] = a0.w;
        As[lc + 0][lr + 64] = a1.x; As[lc + 1][lr + 64] = a1.y; As[lc + 2][lr + 64] = a1.z; As[lc + 3][lr + 64] = a1.w;
        Bs[lc + 0][lr] = b0.x; Bs[lc + 1][lr] = b0.y; Bs[lc + 2][lr] = b0.z; Bs[lc + 3][lr] = b0.w;
        Bs[lc + 0][lr + 64] = b1.x; Bs[lc + 1][lr + 64] = b1.y; Bs[lc + 2][lr + 64] = b1.z; Bs[lc + 3][lr + 64] = b1.w;
        __syncthreads();
#pragma unroll
        for (int k = 0; k < 16; k++) {
            float aF[8], bF[8];
            float4 t0 = *(const float4*)&As[k][ty * 8];
            float4 t1 = *(const float4*)&As[k][ty * 8 + 4];
            float4 t2 = *(const float4*)&Bs[k][tx * 8];
            float4 t3 = *(const float4*)&Bs[k][tx * 8 + 4];
            aF[0] = t0.x; aF[1] = t0.y; aF[2] = t0.z; aF[3] = t0.w;
            aF[4] = t1.x; aF[5] = t1.y; aF[6] = t1.z; aF[7] = t1.w;
            bF[0] = t2.x; bF[1] = t2.y; bF[2] = t2.z; bF[3] = t2.w;
            bF[4] = t3.x; bF[5] = t3.y; bF[6] = t3.z; bF[7] = t3.w;
#pragma unroll
            for (int i = 0; i < 8; i++)
#pragma unroll
                for (int j = 0; j < 8; j++)
                    acc[i][j] = fmaf(aF[i], bF[j], acc[i][j]);
        }
    }

    float cj[8];
    if (mode == 2) {
#pragma unroll
        for (int j = 0; j < 8; j++) cj[j] = nrm[bn + tx * 8 + j];
    } else {
#pragma unroll
        for (int j = 0; j < 8; j++) cj[j] = bias[bn + tx * 8 + j];
    }
#pragma unroll
    for (int i = 0; i < 8; i++) {
        const int row = bm + ty * 8 + i;
        float* Crow = C + (size_t)row * N + bn + tx * 8;
        if (mode == 2) {
            const float ni = nrm[row];
#pragma unroll
            for (int j = 0; j < 8; j++) {
                float v = acc[i][j] / (ni * cj[j]);
                v = fmaxf(v, 1e-6f);
                acc[i][j] = 1.f - v;
            }
        } else {
#pragma unroll
            for (int j = 0; j < 8; j++) {
                float v = acc[i][j] + cj[j];
                if (mode == 1) v = fmaxf(v, 0.f);
                acc[i][j] = v;
            }
        }
        *(float4*)(Crow)     = make_float4(acc[i][0], acc[i][1], acc[i][2], acc[i][3]);
        *(float4*)(Crow + 4) = make_float4(acc[i][4], acc[i][5], acc[i][6], acc[i][7]);
    }
}

// ---------------- row-norm kernel ----------------
__global__ void norm_k(const float* __restrict__ e, float* __restrict__ nrm)
{
    const int row  = blockIdx.x * 8 + (threadIdx.x >> 5);
    const int lane = threadIdx.x & 31;
    const float* p = e + (size_t)row * 256;
    float s = 0.f;
#pragma unroll
    for (int i = 0; i < 8; i++) { float v = p[lane + i * 32]; s += v * v; }
#pragma unroll
    for (int o = 16; o; o >>= 1) s += __shfl_xor_sync(0xffffffffu, s, o);
    if (lane == 0) nrm[row] = sqrtf(s);
}

// ---------------- LSTM scan helpers ----------------
#define NCL 8
#define SCAN_THREADS 512

__device__ __forceinline__ uint32_t s2u(const void* p)
{
    uint32_t a;
    asm("{ .reg .u64 t; cvta.to.shared.u64 t, %1; cvt.u32.u64 %0, t; }" : "=r"(a) : "l"(p));
    return a;
}
__device__ __forceinline__ uint32_t mapa_u32(uint32_t la, uint32_t rank)
{
    uint32_t ra;
    asm("mapa.shared::cluster.u32 %0, %1, %2;" : "=r"(ra) : "r"(la), "r"(rank));
    return ra;
}
// plain remote DSMEM store (no mbarrier involvement)
__device__ __forceinline__ void st_cluster_f32(uint32_t ra, float v)
{
    asm volatile("st.shared::cluster.f32 [%0], %1;" :: "r"(ra), "f"(v) : "memory");
}
__device__ __forceinline__ float tanha(float x)
{
    float y; asm("tanh.approx.f32 %0, %1;" : "=f"(y) : "f"(x)); return y;
}
__device__ __forceinline__ float sigm(float x)
{
    return fmaf(tanha(0.5f * x), 0.5f, 0.5f);
}
__device__ __forceinline__ void fma2(unsigned long long& acc, unsigned long long a, unsigned long long b)
{
    asm("fma.rn.f32x2 %0, %1, %2, %3;" : "=l"(acc) : "l"(a), "l"(b), "l"(acc));
}

// ---------------- LSTM scan: 2 clusters of 8 CTAs (fwd / bwd) ----------------
// R2 structure, but synchronization = SENTINEL POLLING instead of mbarriers:
//  - producers write h via plain st.shared::cluster (4B stores, atomic)
//  - buffers pre-filled with NaN sentinel; scout warp (15) polls its CTA's
//    256 data words, then raises a local flag; other warps spin on the flag
//  - warp 0 re-sentinels the consumed buffer after __syncthreads and BEFORE
//    its sends (transitive causality makes reuse safe, as with expect-rearm)
__global__ void __cluster_dims__(NCL, 1, 1) __launch_bounds__(SCAN_THREADS, 1)
lstm_scan(const float* __restrict__ xsf, const float* __restrict__ xsb,
          const float* __restrict__ whf, const float* __restrict__ whb,
          float* __restrict__ hout)
{
    // padded h layout: 4 segments of 64 data floats + 4 pad, stride 68 words
    __shared__ __align__(16) float hsh[2][4 * 68];
    __shared__ float zsh[128];
    __shared__ int flags[2];

    const int t   = threadIdx.x;
    const int dir = blockIdx.x / NCL;                 // 0 = forward, 1 = backward
    const int lane = t & 31;
    const int warp = t >> 5;
    uint32_t rank;
    asm("mov.u32 %0, %%cluster_ctarank;" : "=r"(rank));

    const float* xs  = dir ? xsb : xsf;
    const float* Whh = dir ? whb : whf;

    const int r  = t >> 2;                // gate-row within CTA: 0..127
    const int q  = t & 3;                 // quarter of the dot product
    const int gg = r >> 5;                // gate index 0..3 (i,f,g,o)
    const int uu = r & 31;                // unit within CTA
    const int G  = gg * HDIM + (int)rank * 32 + uu;   // global gate row 0..1023

    // this thread's 64 weights as packed f32x2 pairs (register-resident)
    ulonglong2 wv[8], wv2[8];
    const ulonglong2* wp = reinterpret_cast<const ulonglong2*>(Whh + (size_t)G * HDIM + q * 64);
#pragma unroll
    for (int i = 0; i < 8; i++) wv[i]  = wp[i];
#pragma unroll
    for (int i = 0; i < 8; i++) wv2[i] = wp[8 + i];

    // init: buffer 0 (receives h(0)) -> sentinel ; buffer 1 (h(-1)=0) -> zeros
    for (int i = t; i < 4 * 68; i += SCAN_THREADS) {
        ((uint32_t*)&hsh[0][0])[i] = SENT;
        hsh[1][i] = 0.f;
    }
    if (t == 0) { flags[0] = -1; flags[1] = 0; }

    // word offset (within a buffer) of a global hidden index
    //   word(i) = (i>>6)*68 + (i&63)
    // warp-0 sender constants: remote slot of h index rank*32+lane in all CTAs
    uint32_t rdst[NCL];
    {
        const int hidx = (int)rank * 32 + lane;
        const int word = (hidx >> 6) * 68 + (hidx & 63);
        const uint32_t la = s2u(&hsh[0][word]);
#pragma unroll
        for (int p = 0; p < NCL; p++) rdst[p] = mapa_u32(la, (uint32_t)p);
    }
    // warp-0 reset offsets / scout poll offsets: h indices lane+32k, k=0..7
    int woff[8];
#pragma unroll
    for (int k = 0; k < 8; k++) {
        const int idx = lane + 32 * k;
        woff[k] = (idx >> 6) * 68 + (idx & 63);
    }

    float creg = 0.f;
    __syncthreads();
    // peers' sentinel init must be complete before any remote store arrives
    asm volatile("barrier.cluster.arrive.aligned;" ::: "memory");
    asm volatile("barrier.cluster.wait.aligned;"  ::: "memory");

    // prefetch x for the first step (q==0 lanes only)
    float xnext = 0.f;
    if (q == 0) {
        const int trow0 = dir ? (TLEN - 1) : 0;
        xnext = xs[(size_t)trow0 * 1024 + G];
    }

    for (int s = 0; s < TLEN; s++) {
        const int rb = (s + 1) & 1;        // buffer holding h(s-1)
        const int wb = s & 1;              // buffer receiving h(s)

        if (s > 0) {
            if (warp == 15) {
                // scout: poll the 256 data words of buffer rb
                volatile uint32_t* hb = (volatile uint32_t*)&hsh[rb][0];
                for (;;) {
                    uint32_t bad = 0;
#pragma unroll
                    for (int k = 0; k < 8; k++) bad |= (hb[woff[k]] == SENT);
                    if (__all_sync(0xffffffffu, bad == 0)) break;
                }
                if (lane == 0) *(volatile int*)&flags[rb] = s;
            } else {
                while (*(volatile int*)&flags[rb] != s) { }
            }
            asm volatile("" ::: "memory");
        }

        const int trow = dir ? (TLEN - 1 - s) : s;
        const float xcur = xnext;
        if (q == 0 && s + 1 < TLEN) {
            const int tnext = dir ? (TLEN - 2 - s) : (s + 1);
            xnext = xs[(size_t)tnext * 1024 + G];
        }

        // z_partial = W_slice . h(s-1): packed f32x2 FMAs, h loaded as b64 pairs
        const ulonglong2* hp = reinterpret_cast<const ulonglong2*>(&hsh[rb][q * 68]);
        unsigned long long acc2 = 0ull;
#pragma unroll
        for (int i = 0; i < 8; i++) {
            ulonglong2 hv = hp[i];
            fma2(acc2, wv[i].x, hv.x);
            fma2(acc2, wv[i].y, hv.y);
        }
#pragma unroll
        for (int i = 0; i < 8; i++) {
            ulonglong2 hv = hp[8 + i];
            fma2(acc2, wv2[i].x, hv.x);
            fma2(acc2, wv2[i].y, hv.y);
        }
        float alo, ahi;
        asm("mov.b64 {%0, %1}, %2;" : "=f"(alo), "=f"(ahi) : "l"(acc2));
        float acc = alo + ahi;
        acc += __shfl_xor_sync(0xffffffffu, acc, 1);
        acc += __shfl_xor_sync(0xffffffffu, acc, 2);
        if (q == 0) zsh[r] = acc + xcur;
        __syncthreads();   // all reads of buffer rb complete; zsh visible

        if (t < 32) {      // gate warp: reset rb, gates, send, store
            // re-sentinel consumed buffer rb (for h(s+1)); precedes our sends
            uint32_t* hb = (uint32_t*)&hsh[rb][0];
#pragma unroll
            for (int k = 0; k < 8; k++) hb[woff[k]] = SENT;

            const float zi = zsh[t];
            const float zf = zsh[32 + t];
            const float zg = zsh[64 + t];
            const float zo = zsh[96 + t];
            const float si = sigm(zi);
            const float sf = sigm(zf);
            const float so = sigm(zo);
            const float c  = sf * creg + si * tanha(zg);
            creg = c;
            const float h = so * tanha(c);

            if (s + 1 < TLEN) {
                const uint32_t doff = (uint32_t)wb * 1088u;   // buffer stride in bytes
#pragma unroll
                for (int p = 0; p < NCL; p++)
                    st_cluster_f32(rdst[p] + doff, h);
            }
            hout[(size_t)trow * 512 + dir * 256 + (int)rank * 32 + t] = h;
        }
    }

    // don't exit while peers may still be consuming our last stores
    asm volatile("barrier.cluster.arrive.aligned;" ::: "memory");
    asm volatile("barrier.cluster.wait.aligned;"  ::: "memory");
}

// ---------------- launcher ----------------
extern "C" void kernel_launch(void* const* d_in, const int* in_sizes, int n_in,
                              void* d_out, int out_size)
{
    (void)in_sizes; (void)n_in; (void)out_size;
    const float* x     = (const float*)d_in[0];
    const float* wih0f = (const float*)d_in[1];
    const float* whh0f = (const float*)d_in[2];
    const float* b0f   = (const float*)d_in[3];
    const float* wih0b = (const float*)d_in[4];
    const float* whh0b = (const float*)d_in[5];
    const float* b0b   = (const float*)d_in[6];
    const float* wih1f = (const float*)d_in[7];
    const float* whh1f = (const float*)d_in[8];
    const float* b1f   = (const float*)d_in[9];
    const float* wih1b = (const float*)d_in[10];
    const float* whh1b = (const float*)d_in[11];
    const float* b1b   = (const float*)d_in[12];
    const float* fc1w  = (const float*)d_in[13];
    const float* fc1b  = (const float*)d_in[14];
    const float* fc2w  = (const float*)d_in[15];
    const float* fc2b  = (const float*)d_in[16];
    float* out = (float*)d_out;

    float *xsf, *xsb, *h1, *h2, *z, *e, *nrm;
    cudaGetSymbolAddress((void**)&xsf, g_xsf);
    cudaGetSymbolAddress((void**)&xsb, g_xsb);
    cudaGetSymbolAddress((void**)&h1,  g_h1);
    cudaGetSymbolAddress((void**)&h2,  g_h2);
    cudaGetSymbolAddress((void**)&z,   g_z);
    cudaGetSymbolAddress((void**)&e,   g_e);
    cudaGetSymbolAddress((void**)&nrm, g_nrm);

    const dim3 blk(256);

    // layer 0: input projections (M=4096, N=1024, K=128)
    gemm_k<<<dim3(8, 32), blk>>>(x, wih0f, b0f, nullptr, xsf, TLEN, 1024, 128, 0);
    gemm_k<<<dim3(8, 32), blk>>>(x, wih0b, b0b, nullptr, xsb, TLEN, 1024, 128, 0);
    // layer 0 scan
    lstm_scan<<<16, SCAN_THREADS>>>(xsf, xsb, whh0f, whh0b, h1);
    // layer 1: input projections (K=512)
    gemm_k<<<dim3(8, 32), blk>>>(h1, wih1f, b1f, nullptr, xsf, TLEN, 1024, 512, 0);
    gemm_k<<<dim3(8, 32), blk>>>(h1, wih1b, b1b, nullptr, xsb, TLEN, 1024, 512, 0);
    // layer 1 scan
    lstm_scan<<<16, SCAN_THREADS>>>(xsf, xsb, whh1f, whh1b, h2);
    // fc1 (relu), fc2
    gemm_k<<<dim3(2, 32), blk>>>(h2, fc1w, fc1b, nullptr, z, TLEN, 256, 512, 1);
    gemm_k<<<dim3(2, 32), blk>>>(z,  fc2w, fc2b, nullptr, e, TLEN, 256, 256, 0);
    // norms + cosine-distance matrix (fused epilogue)
    norm_k<<<TLEN / 8, 256>>>(e, nrm);
    gemm_k<<<dim3(32, 32), blk>>>(e, e, nullptr, nrm, out, TLEN, TLEN, 256, 2);
}

// round 7
// speedup vs baseline: 1.1331x; 1.1331x over previous
#include <cuda_runtime.h>
#include <cstdint>
#include <math.h>

#define TLEN 4096
#define HDIM 256

// ---------------- scratch (static device arrays; no allocation) ----------------
__device__ float g_xsf[TLEN * 1024];   // 16 MB  input-proj forward (reused per layer)
__device__ float g_xsb[TLEN * 1024];   // 16 MB  input-proj backward
__device__ float g_h1 [TLEN * 512];    // 8 MB   layer0 output [hf | hb]
__device__ float g_h2 [TLEN * 512];    // 8 MB   layer1 output
__device__ float g_z  [TLEN * 256];    // 4 MB   fc1 output
__device__ float g_e  [TLEN * 256];    // 4 MB   fc2 output
__device__ float g_nrm[TLEN];          // reciprocal row norms of e

// ---------------- generic 128x128 SGEMM: C = A(MxK) * B(NxK)^T (+epilogue) ------
// mode 0: C += bias ; mode 1: relu(C + bias) ; mode 2: cosine-distance epilogue
// (mode 2 uses nrm[] = 1/||row||, so the epilogue is multiply-only)
__global__ __launch_bounds__(256, 2)
void gemm_k(const float* __restrict__ A, const float* __restrict__ B,
            const float* __restrict__ bias, const float* __restrict__ nrm,
            float* __restrict__ C, int M, int N, int K, int mode)
{
    __shared__ float As[16][128];
    __shared__ float Bs[16][128];

    const int tid = threadIdx.x;
    const int bm = blockIdx.y << 7;
    const int bn = blockIdx.x << 7;
    const int tx = tid & 15;
    const int ty = tid >> 4;
    const int lr = tid >> 2;
    const int lc = (tid & 3) << 2;

    const float* Ap = A + (size_t)(bm + lr) * K + lc;
    const float* Bp = B + (size_t)(bn + lr) * K + lc;

    float acc[8][8];
#pragma unroll
    for (int i = 0; i < 8; i++)
#pragma unroll
        for (int j = 0; j < 8; j++) acc[i][j] = 0.f;

    for (int k0 = 0; k0 < K; k0 += 16) {
        float4 a0 = *(const float4*)(Ap + k0);
        float4 a1 = *(const float4*)(Ap + (size_t)64 * K + k0);
        float4 b0 = *(const float4*)(Bp + k0);
        float4 b1 = *(const float4*)(Bp + (size_t)64 * K + k0);
        __syncthreads();
        As[lc + 0][lr] = a0.x; As[lc + 1][lr] = a0.y; As[lc + 2][lr] = a0.z; As[lc + 3][lr] = a0.w;
        As[lc + 0][lr + 64] = a1.x; As[lc + 1][lr + 64] = a1.y; As[lc + 2][lr + 64] = a1.z; As[lc + 3][lr + 64] = a1.w;
        Bs[lc + 0][lr] = b0.x; Bs[lc + 1][lr] = b0.y; Bs[lc + 2][lr] = b0.z; Bs[lc + 3][lr] = b0.w;
        Bs[lc + 0][lr + 64] = b1.x; Bs[lc + 1][lr + 64] = b1.y; Bs[lc + 2][lr + 64] = b1.z; Bs[lc + 3][lr + 64] = b1.w;
        __syncthreads();
#pragma unroll
        for (int k = 0; k < 16; k++) {
            float aF[8], bF[8];
            float4 t0 = *(const float4*)&As[k][ty * 8];
            float4 t1 = *(const float4*)&As[k][ty * 8 + 4];
            float4 t2 = *(const float4*)&Bs[k][tx * 8];
            float4 t3 = *(const float4*)&Bs[k][tx * 8 + 4];
            aF[0] = t0.x; aF[1] = t0.y; aF[2] = t0.z; aF[3] = t0.w;
            aF[4] = t1.x; aF[5] = t1.y; aF[6] = t1.z; aF[7] = t1.w;
            bF[0] = t2.x; bF[1] = t2.y; bF[2] = t2.z; bF[3] = t2.w;
            bF[4] = t3.x; bF[5] = t3.y; bF[6] = t3.z; bF[7] = t3.w;
#pragma unroll
            for (int i = 0; i < 8; i++)
#pragma unroll
                for (int j = 0; j < 8; j++)
                    acc[i][j] = fmaf(aF[i], bF[j], acc[i][j]);
        }
    }

    float cj[8];
    if (mode == 2) {
#pragma unroll
        for (int j = 0; j < 8; j++) cj[j] = nrm[bn + tx * 8 + j];   // 1/||col row||
    } else {
#pragma unroll
        for (int j = 0; j < 8; j++) cj[j] = bias[bn + tx * 8 + j];
    }
#pragma unroll
    for (int i = 0; i < 8; i++) {
        const int row = bm + ty * 8 + i;
        float* Crow = C + (size_t)row * N + bn + tx * 8;
        if (mode == 2) {
            const float ri = nrm[row];
#pragma unroll
            for (int j = 0; j < 8; j++) {
                float v = acc[i][j] * ri * cj[j];
                v = fmaxf(v, 1e-6f);
                acc[i][j] = 1.f - v;
            }
        } else {
#pragma unroll
            for (int j = 0; j < 8; j++) {
                float v = acc[i][j] + cj[j];
                if (mode == 1) v = fmaxf(v, 0.f);
                acc[i][j] = v;
            }
        }
        *(float4*)(Crow)     = make_float4(acc[i][0], acc[i][1], acc[i][2], acc[i][3]);
        *(float4*)(Crow + 4) = make_float4(acc[i][4], acc[i][5], acc[i][6], acc[i][7]);
    }
}

// ---------------- row-norm kernel: stores RECIPROCAL norms ----------------
__global__ void norm_k(const float* __restrict__ e, float* __restrict__ nrm)
{
    const int row  = blockIdx.x * 8 + (threadIdx.x >> 5);
    const int lane = threadIdx.x & 31;
    const float* p = e + (size_t)row * 256;
    float s = 0.f;
#pragma unroll
    for (int i = 0; i < 8; i++) { float v = p[lane + i * 32]; s += v * v; }
#pragma unroll
    for (int o = 16; o; o >>= 1) s += __shfl_xor_sync(0xffffffffu, s, o);
    if (lane == 0) nrm[row] = 1.0f / sqrtf(s);
}

// ---------------- LSTM scan helpers ----------------
#define NCL 8
#define SCAN_THREADS 512

__device__ __forceinline__ uint32_t s2u(const void* p)
{
    uint32_t a;
    asm("{ .reg .u64 t; cvta.to.shared.u64 t, %1; cvt.u32.u64 %0, t; }" : "=r"(a) : "l"(p));
    return a;
}
__device__ __forceinline__ uint32_t mapa_u32(uint32_t la, uint32_t rank)
{
    uint32_t ra;
    asm("mapa.shared::cluster.u32 %0, %1, %2;" : "=r"(ra) : "r"(la), "r"(rank));
    return ra;
}
__device__ __forceinline__ void st_async_f32(uint32_t ra_data, float v, uint32_t ra_bar)
{
    asm volatile("st.async.shared::cluster.mbarrier::complete_tx::bytes.u32 [%0], %1, [%2];"
                 :: "r"(ra_data), "r"(__float_as_uint(v)), "r"(ra_bar) : "memory");
}
__device__ __forceinline__ void mbar_init(uint32_t bar, uint32_t cnt)
{
    asm volatile("mbarrier.init.shared.b64 [%0], %1;" :: "r"(bar), "r"(cnt) : "memory");
}
__device__ __forceinline__ void mbar_expect(uint32_t bar, uint32_t bytes)
{
    asm volatile("mbarrier.arrive.expect_tx.shared.b64 _, [%0], %1;" :: "r"(bar), "r"(bytes) : "memory");
}
__device__ __forceinline__ void mbar_wait(uint32_t bar, uint32_t phase)
{
    asm volatile(
        "{\n\t"
        ".reg .pred P%=;\n\t"
        "W%=:\n\t"
        "mbarrier.try_wait.parity.acquire.cta.shared::cta.b64 P%=, [%0], %1, 0x989680;\n\t"
        "@P%= bra.uni D%=;\n\t"
        "bra.uni W%=;\n\t"
        "D%=:\n\t"
        "}"
        :: "r"(bar), "r"(phase) : "memory");
}
__device__ __forceinline__ float tanha(float x)
{
    float y; asm("tanh.approx.f32 %0, %1;" : "=f"(y) : "f"(x)); return y;
}
__device__ __forceinline__ float sigm(float x)
{
    return fmaf(tanha(0.5f * x), 0.5f, 0.5f);
}
__device__ __forceinline__ void fma2(unsigned long long& acc, unsigned long long a, unsigned long long b)
{
    asm("fma.rn.f32x2 %0, %1, %2, %3;" : "=l"(acc) : "l"(a), "l"(b), "l"(acc));
}

// ---------------- LSTM scan: 2 clusters of 8 CTAs (fwd / bwd) ----------------
// R2 skeleton (mbarrier + scalar st.async — the proven best), with:
//  - matvec split into TWO independent f32x2 FMA chains (dep 128 -> 64 cyc)
//  - NO shfl reduce: every lane writes its quarter-partial to zsh[t]
//    (t = row*4 + q), and the gate warp does the 4-way add from one LDS.128
//    per gate after __syncthreads.
__global__ void __cluster_dims__(NCL, 1, 1) __launch_bounds__(SCAN_THREADS, 1)
lstm_scan(const float* __restrict__ xsf, const float* __restrict__ xsb,
          const float* __restrict__ whf, const float* __restrict__ whb,
          float* __restrict__ hout)
{
    // padded h layout: 4 segments of 64 floats, stride 68 words -> conflict-free
    __shared__ __align__(16) float hsh[2][4 * 68];
    __shared__ __align__(16) float zsh[512];      // partials: [row*4 + q]
    __shared__ __align__(8) unsigned long long mbar[2];

    const int t   = threadIdx.x;
    const int dir = blockIdx.x / NCL;                 // 0 = forward, 1 = backward
    uint32_t rank;
    asm("mov.u32 %0, %%cluster_ctarank;" : "=r"(rank));

    const float* xs  = dir ? xsb : xsf;
    const float* Whh = dir ? whb : whf;

    const int r  = t >> 2;                // gate-row within CTA: 0..127
    const int q  = t & 3;                 // quarter of the dot product
    const int gg = r >> 5;                // gate index 0..3 (i,f,g,o)
    const int uu = r & 31;                // unit within CTA
    const int G  = gg * HDIM + (int)rank * 32 + uu;   // global gate row 0..1023

    // this thread's 64 weights as packed f32x2 pairs (register-resident)
    ulonglong2 wv[8], wv2[8];
    const ulonglong2* wp = reinterpret_cast<const ulonglong2*>(Whh + (size_t)G * HDIM + q * 64);
#pragma unroll
    for (int i = 0; i < 8; i++) wv[i]  = wp[i];
#pragma unroll
    for (int i = 0; i < 8; i++) wv2[i] = wp[8 + i];

    for (int i = t; i < 4 * 68; i += SCAN_THREADS) { hsh[0][i] = 0.f; hsh[1][i] = 0.f; }

    const uint32_t bar0 = s2u(&mbar[0]);
    if (t == 0) {
        mbar_init(bar0, 1);
        mbar_init(bar0 + 8, 1);
        mbar_expect(bar0, 1024);
        mbar_expect(bar0 + 8, 1024);
    }

    // warp-0 sender constants: remote slot of h index rank*32+lane in all CTAs
    uint32_t rdst[NCL], rbar[NCL];
    {
        const int hidx = (int)rank * 32 + (t & 31);
        const int word = (hidx >> 6) * 68 + (hidx & 63);
        const uint32_t la = s2u(&hsh[0][word]);
#pragma unroll
        for (int p = 0; p < NCL; p++) {
            rdst[p] = mapa_u32(la,   (uint32_t)p);
            rbar[p] = mapa_u32(bar0, (uint32_t)p);
        }
    }

    float creg = 0.f;
    __syncthreads();
    // all CTAs' barriers must be live before any remote st.async
    asm volatile("barrier.cluster.arrive.aligned;" ::: "memory");
    asm volatile("barrier.cluster.wait.aligned;"  ::: "memory");

    // prefetch xs for the first step (q==0 lanes only; folded into partial)
    float xnext = 0.f;
    if (q == 0) {
        const int trow0 = dir ? (TLEN - 1) : 0;
        xnext = xs[(size_t)trow0 * 1024 + G];
    }

    int ph0 = 0, ph1 = 0;
    for (int s = 0; s < TLEN; s++) {
        const int rb = (s + 1) & 1;        // buffer holding h(s-1)
        const int wb = s & 1;              // buffer receiving h(s)
        if (s > 0) {
            if (rb == 0) { mbar_wait(bar0, ph0);     ph0 ^= 1; if (t == 0) mbar_expect(bar0, 1024); }
            else         { mbar_wait(bar0 + 8, ph1); ph1 ^= 1; if (t == 0) mbar_expect(bar0 + 8, 1024); }
        }

        const int trow = dir ? (TLEN - 1 - s) : s;
        const float xcur = xnext;
        if (q == 0 && s + 1 < TLEN) {
            const int tnext = dir ? (TLEN - 2 - s) : (s + 1);
            xnext = xs[(size_t)tnext * 1024 + G];
        }

        // quarter-partial dot: TWO independent f32x2 chains
        const ulonglong2* hp = reinterpret_cast<const ulonglong2*>(&hsh[rb][q * 68]);
        unsigned long long a0 = 0ull, a1 = 0ull;
#pragma unroll
        for (int i = 0; i < 8; i++) {
            ulonglong2 hv = hp[i];
            fma2(a0, wv[i].x, hv.x);
            fma2(a1, wv[i].y, hv.y);
        }
#pragma unroll
        for (int i = 0; i < 8; i++) {
            ulonglong2 hv = hp[8 + i];
            fma2(a0, wv2[i].x, hv.x);
            fma2(a1, wv2[i].y, hv.y);
        }
        float f0, f1, f2, f3;
        asm("mov.b64 {%0, %1}, %2;" : "=f"(f0), "=f"(f1) : "l"(a0));
        asm("mov.b64 {%0, %1}, %2;" : "=f"(f2), "=f"(f3) : "l"(a1));
        zsh[t] = ((f0 + f1) + (f2 + f3)) + xcur;    // partial; x folded into q==0
        __syncthreads();   // all partials visible; all reads of buffer rb done

        if (t < 32) {      // gate warp: 4-way adds, gates, send, store
            const float4 pi = *(const float4*)&zsh[(0 * 32 + t) * 4];
            const float4 pf = *(const float4*)&zsh[(1 * 32 + t) * 4];
            const float4 pg = *(const float4*)&zsh[(2 * 32 + t) * 4];
            const float4 po = *(const float4*)&zsh[(3 * 32 + t) * 4];
            const float zi = (pi.x + pi.y) + (pi.z + pi.w);
            const float zf = (pf.x + pf.y) + (pf.z + pf.w);
            const float zg = (pg.x + pg.y) + (pg.z + pg.w);
            const float zo = (po.x + po.y) + (po.z + po.w);
            const float si = sigm(zi);
            const float sf = sigm(zf);
            const float so = sigm(zo);
            const float c  = sf * creg + si * tanha(zg);
            creg = c;
            const float h = so * tanha(c);

            if (s + 1 < TLEN) {
                const uint32_t doff = (uint32_t)wb * 1088u;   // buffer stride 4*68*4 B
                const uint32_t boff = (uint32_t)wb * 8u;
#pragma unroll
                for (int p = 0; p < NCL; p++)
                    st_async_f32(rdst[p] + doff, h, rbar[p] + boff);
            }
            hout[(size_t)trow * 512 + dir * 256 + (int)rank * 32 + t] = h;
        }
    }

    // don't exit while peers may still be consuming our last stores
    asm volatile("barrier.cluster.arrive.aligned;" ::: "memory");
    asm volatile("barrier.cluster.wait.aligned;"  ::: "memory");
}

// ---------------- launcher ----------------
extern "C" void kernel_launch(void* const* d_in, const int* in_sizes, int n_in,
                              void* d_out, int out_size)
{
    (void)in_sizes; (void)n_in; (void)out_size;
    const float* x     = (const float*)d_in[0];
    const float* wih0f = (const float*)d_in[1];
    const float* whh0f = (const float*)d_in[2];
    const float* b0f   = (const float*)d_in[3];
    const float* wih0b = (const float*)d_in[4];
    const float* whh0b = (const float*)d_in[5];
    const float* b0b   = (const float*)d_in[6];
    const float* wih1f = (const float*)d_in[7];
    const float* whh1f = (const float*)d_in[8];
    const float* b1f   = (const float*)d_in[9];
    const float* wih1b = (const float*)d_in[10];
    const float* whh1b = (const float*)d_in[11];
    const float* b1b   = (const float*)d_in[12];
    const float* fc1w  = (const float*)d_in[13];
    const float* fc1b  = (const float*)d_in[14];
    const float* fc2w  = (const float*)d_in[15];
    const float* fc2b  = (const float*)d_in[16];
    float* out = (float*)d_out;

    float *xsf, *xsb, *h1, *h2, *z, *e, *nrm;
    cudaGetSymbolAddress((void**)&xsf, g_xsf);
    cudaGetSymbolAddress((void**)&xsb, g_xsb);
    cudaGetSymbolAddress((void**)&h1,  g_h1);
    cudaGetSymbolAddress((void**)&h2,  g_h2);
    cudaGetSymbolAddress((void**)&z,   g_z);
    cudaGetSymbolAddress((void**)&e,   g_e);
    cudaGetSymbolAddress((void**)&nrm, g_nrm);

    const dim3 blk(256);

    // layer 0: input projections (M=4096, N=1024, K=128)
    gemm_k<<<dim3(8, 32), blk>>>(x, wih0f, b0f, nullptr, xsf, TLEN, 1024, 128, 0);
    gemm_k<<<dim3(8, 32), blk>>>(x, wih0b, b0b, nullptr, xsb, TLEN, 1024, 128, 0);
    // layer 0 scan
    lstm_scan<<<16, SCAN_THREADS>>>(xsf, xsb, whh0f, whh0b, h1);
    // layer 1: input projections (K=512)
    gemm_k<<<dim3(8, 32), blk>>>(h1, wih1f, b1f, nullptr, xsf, TLEN, 1024, 512, 0);
    gemm_k<<<dim3(8, 32), blk>>>(h1, wih1b, b1b, nullptr, xsb, TLEN, 1024, 512, 0);
    // layer 1 scan
    lstm_scan<<<16, SCAN_THREADS>>>(xsf, xsb, whh1f, whh1b, h2);
    // fc1 (relu), fc2
    gemm_k<<<dim3(2, 32), blk>>>(h2, fc1w, fc1b, nullptr, z, TLEN, 256, 512, 1);
    gemm_k<<<dim3(2, 32), blk>>>(z,  fc2w, fc2b, nullptr, e, TLEN, 256, 256, 0);
    // reciprocal norms + cosine-distance matrix (multiply-only epilogue)
    norm_k<<<TLEN / 8, 256>>>(e, nrm);
    gemm_k<<<dim3(32, 32), blk>>>(e, e, nullptr, nrm, out, TLEN, TLEN, 256, 2);
}

// round 8
// speedup vs baseline: 1.5001x; 1.3239x over previous
#include <cuda_runtime.h>
#include <cstdint>
#include <math.h>

#define TLEN 4096
#define HDIM 256

// ---------------- scratch (static device arrays; no allocation) ----------------
__device__ float g_xsf[TLEN * 1024];   // 16 MB  input-proj forward (reused per layer)
__device__ float g_xsb[TLEN * 1024];   // 16 MB  input-proj backward
__device__ float g_h1 [TLEN * 512];    // 8 MB   layer0 output [hf | hb]
__device__ float g_h2 [TLEN * 512];    // 8 MB   layer1 output
__device__ float g_z  [TLEN * 256];    // 4 MB   fc1 output
__device__ float g_e  [TLEN * 256];    // 4 MB   fc2 output
__device__ float g_nrm[TLEN];          // reciprocal row norms of e

// ---------------- generic 128x128 SGEMM: C = A(MxK) * B(NxK)^T (+epilogue) ------
// mode 0: C += bias ; mode 1: relu(C + bias) ; mode 2: cosine-distance epilogue
__global__ __launch_bounds__(256, 1)
void gemm_k(const float* __restrict__ A, const float* __restrict__ B,
            const float* __restrict__ bias, const float* __restrict__ nrm,
            float* __restrict__ C, int M, int N, int K, int mode)
{
    __shared__ float As[16][128];
    __shared__ float Bs[16][128];

    const int tid = threadIdx.x;
    const int bm = blockIdx.y << 7;
    const int bn = blockIdx.x << 7;
    const int tx = tid & 15;
    const int ty = tid >> 4;
    const int lr = tid >> 2;
    const int lc = (tid & 3) << 2;

    const float* Ap = A + (size_t)(bm + lr) * K + lc;
    const float* Bp = B + (size_t)(bn + lr) * K + lc;

    float acc[8][8];
#pragma unroll
    for (int i = 0; i < 8; i++)
#pragma unroll
        for (int j = 0; j < 8; j++) acc[i][j] = 0.f;

    for (int k0 = 0; k0 < K; k0 += 16) {
        float4 a0 = *(const float4*)(Ap + k0);
        float4 a1 = *(const float4*)(Ap + (size_t)64 * K + k0);
        float4 b0 = *(const float4*)(Bp + k0);
        float4 b1 = *(const float4*)(Bp + (size_t)64 * K + k0);
        __syncthreads();
        As[lc + 0][lr] = a0.x; As[lc + 1][lr] = a0.y; As[lc + 2][lr] = a0.z; As[lc + 3][lr] = a0.w;
        As[lc + 0][lr + 64] = a1.x; As[lc + 1][lr + 64] = a1.y; As[lc + 2][lr + 64] = a1.z; As[lc + 3][lr + 64] = a1.w;
        Bs[lc + 0][lr] = b0.x; Bs[lc + 1][lr] = b0.y; Bs[lc + 2][lr] = b0.z; Bs[lc + 3][lr] = b0.w;
        Bs[lc + 0][lr + 64] = b1.x; Bs[lc + 1][lr + 64] = b1.y; Bs[lc + 2][lr + 64] = b1.z; Bs[lc + 3][lr + 64] = b1.w;
        __syncthreads();
#pragma unroll
        for (int k = 0; k < 16; k++) {
            float aF[8], bF[8];
            float4 t0 = *(const float4*)&As[k][ty * 8];
            float4 t1 = *(const float4*)&As[k][ty * 8 + 4];
            float4 t2 = *(const float4*)&Bs[k][tx * 8];
            float4 t3 = *(const float4*)&Bs[k][tx * 8 + 4];
            aF[0] = t0.x; aF[1] = t0.y; aF[2] = t0.z; aF[3] = t0.w;
            aF[4] = t1.x; aF[5] = t1.y; aF[6] = t1.z; aF[7] = t1.w;
            bF[0] = t2.x; bF[1] = t2.y; bF[2] = t2.z; bF[3] = t2.w;
            bF[4] = t3.x; bF[5] = t3.y; bF[6] = t3.z; bF[7] = t3.w;
#pragma unroll
            for (int i = 0; i < 8; i++)
#pragma unroll
                for (int j = 0; j < 8; j++)
                    acc[i][j] = fmaf(aF[i], bF[j], acc[i][j]);
        }
    }

    float cj[8];
    if (mode == 2) {
#pragma unroll
        for (int j = 0; j < 8; j++) cj[j] = nrm[bn + tx * 8 + j];   // 1/||col row||
    } else {
#pragma unroll
        for (int j = 0; j < 8; j++) cj[j] = bias[bn + tx * 8 + j];
    }
#pragma unroll
    for (int i = 0; i < 8; i++) {
        const int row = bm + ty * 8 + i;
        float* Crow = C + (size_t)row * N + bn + tx * 8;
        if (mode == 2) {
            const float ri = nrm[row];
#pragma unroll
            for (int j = 0; j < 8; j++) {
                float v = acc[i][j] * ri * cj[j];
                v = fmaxf(v, 1e-6f);
                acc[i][j] = 1.f - v;
            }
        } else {
#pragma unroll
            for (int j = 0; j < 8; j++) {
                float v = acc[i][j] + cj[j];
                if (mode == 1) v = fmaxf(v, 0.f);
                acc[i][j] = v;
            }
        }
        *(float4*)(Crow)     = make_float4(acc[i][0], acc[i][1], acc[i][2], acc[i][3]);
        *(float4*)(Crow + 4) = make_float4(acc[i][4], acc[i][5], acc[i][6], acc[i][7]);
    }
}

// ---------------- row-norm kernel: stores RECIPROCAL norms ----------------
__global__ void norm_k(const float* __restrict__ e, float* __restrict__ nrm)
{
    const int row  = blockIdx.x * 8 + (threadIdx.x >> 5);
    const int lane = threadIdx.x & 31;
    const float* p = e + (size_t)row * 256;
    float s = 0.f;
#pragma unroll
    for (int i = 0; i < 8; i++) { float v = p[lane + i * 32]; s += v * v; }
#pragma unroll
    for (int o = 16; o; o >>= 1) s += __shfl_xor_sync(0xffffffffu, s, o);
    if (lane == 0) nrm[row] = 1.0f / sqrtf(s);
}

// ---------------- LSTM scan helpers ----------------
#define NCL 16
#define SCAN_THREADS 256

__device__ __forceinline__ uint32_t s2u(const void* p)
{
    uint32_t a;
    asm("{ .reg .u64 t; cvta.to.shared.u64 t, %1; cvt.u32.u64 %0, t; }" : "=r"(a) : "l"(p));
    return a;
}
__device__ __forceinline__ uint32_t mapa_u32(uint32_t la, uint32_t rank)
{
    uint32_t ra;
    asm("mapa.shared::cluster.u32 %0, %1, %2;" : "=r"(ra) : "r"(la), "r"(rank));
    return ra;
}
__device__ __forceinline__ void st_async_f32(uint32_t ra_data, float v, uint32_t ra_bar)
{
    asm volatile("st.async.shared::cluster.mbarrier::complete_tx::bytes.u32 [%0], %1, [%2];"
                 :: "r"(ra_data), "r"(__float_as_uint(v)), "r"(ra_bar) : "memory");
}
__device__ __forceinline__ void mbar_init(uint32_t bar, uint32_t cnt)
{
    asm volatile("mbarrier.init.shared.b64 [%0], %1;" :: "r"(bar), "r"(cnt) : "memory");
}
__device__ __forceinline__ void mbar_expect(uint32_t bar, uint32_t bytes)
{
    asm volatile("mbarrier.arrive.expect_tx.shared.b64 _, [%0], %1;" :: "r"(bar), "r"(bytes) : "memory");
}
__device__ __forceinline__ void mbar_wait(uint32_t bar, uint32_t phase)
{
    asm volatile(
        "{\n\t"
        ".reg .pred P%=;\n\t"
        "W%=:\n\t"
        "mbarrier.try_wait.parity.acquire.cta.shared::cta.b64 P%=, [%0], %1, 0x989680;\n\t"
        "@P%= bra.uni D%=;\n\t"
        "bra.uni W%=;\n\t"
        "D%=:\n\t"
        "}"
        :: "r"(bar), "r"(phase) : "memory");
}
__device__ __forceinline__ float tanha(float x)
{
    float y; asm("tanh.approx.f32 %0, %1;" : "=f"(y) : "f"(x)); return y;
}
__device__ __forceinline__ float sigm(float x)
{
    return fmaf(tanha(0.5f * x), 0.5f, 0.5f);
}
__device__ __forceinline__ void fma2(unsigned long long& acc, unsigned long long a, unsigned long long b)
{
    asm("fma.rn.f32x2 %0, %1, %2, %3;" : "=l"(acc) : "l"(a), "l"(b), "l"(acc));
}

// ---------------- LSTM scan: 2 clusters of 16 CTAs (fwd / bwd) ----------------
// Each CTA owns 16 hidden units (64 gate rows), 256 threads = 64 rows x 4
// quarters. Halves the per-SM FFMA2 issue floor vs NCL=8 (the measured
// bottleneck). Gate math is computed REDUNDANTLY on both half-warps of warp 0
// (lane l <-> unit l&15); each lane then sends its unit's h to 8 of the 16
// peers. Same mbarrier / expect_tx(1024B) protocol as the proven R2 design.
__global__ void __cluster_dims__(NCL, 1, 1) __launch_bounds__(SCAN_THREADS, 1)
lstm_scan(const float* __restrict__ xsf, const float* __restrict__ xsb,
          const float* __restrict__ whf, const float* __restrict__ whb,
          float* __restrict__ hout)
{
    // padded h layout: 4 segments of 64 floats, stride 68 words -> conflict-free
    __shared__ __align__(16) float hsh[2][4 * 68];
    __shared__ __align__(16) float zsh[SCAN_THREADS];   // partials: [row*4 + q]
    __shared__ __align__(8) unsigned long long mbar[2];

    const int t   = threadIdx.x;
    const int dir = blockIdx.x / NCL;                 // 0 = forward, 1 = backward
    uint32_t rank;
    asm("mov.u32 %0, %%cluster_ctarank;" : "=r"(rank));

    const float* xs  = dir ? xsb : xsf;
    const float* Whh = dir ? whb : whf;

    const int r  = t >> 2;                // gate-row within CTA: 0..63
    const int q  = t & 3;                 // quarter of the dot product
    const int gg = r >> 4;                // gate index 0..3 (i,f,g,o)
    const int uu = r & 15;                // unit within CTA
    const int G  = gg * HDIM + (int)rank * 16 + uu;   // global gate row 0..1023

    // this thread's 64 weights as packed f32x2 pairs (register-resident)
    ulonglong2 wv[8], wv2[8];
    const ulonglong2* wp = reinterpret_cast<const ulonglong2*>(Whh + (size_t)G * HDIM + q * 64);
#pragma unroll
    for (int i = 0; i < 8; i++) wv[i]  = wp[i];
#pragma unroll
    for (int i = 0; i < 8; i++) wv2[i] = wp[8 + i];

    for (int i = t; i < 2 * 4 * 68; i += SCAN_THREADS) ((float*)hsh)[i] = 0.f;

    const uint32_t bar0 = s2u(&mbar[0]);
    if (t == 0) {
        mbar_init(bar0, 1);
        mbar_init(bar0 + 8, 1);
        mbar_expect(bar0, 1024);
        mbar_expect(bar0 + 8, 1024);
    }

    // warp-0 sender constants: lane l owns unit (l&15); sends to 8 dests
    // p = (l>>4)*8 + k. Remote slot of h index rank*16 + (l&15).
    uint32_t rdst[8], rbar[8];
    {
        const int lane = t & 31;
        const int hidx = (int)rank * 16 + (lane & 15);
        const int word = (hidx >> 6) * 68 + (hidx & 63);
        const uint32_t la = s2u(&hsh[0][word]);
        const uint32_t pb = (uint32_t)((lane >> 4) * 8);
#pragma unroll
        for (int k = 0; k < 8; k++) {
            rdst[k] = mapa_u32(la,   pb + k);
            rbar[k] = mapa_u32(bar0, pb + k);
        }
    }

    float creg = 0.f;
    __syncthreads();
    // all CTAs' barriers must be live before any remote st.async
    asm volatile("barrier.cluster.arrive.aligned;" ::: "memory");
    asm volatile("barrier.cluster.wait.aligned;"  ::: "memory");

    // prefetch xs for the first step (q==0 lanes only; folded into partial)
    float xnext = 0.f;
    if (q == 0) {
        const int trow0 = dir ? (TLEN - 1) : 0;
        xnext = xs[(size_t)trow0 * 1024 + G];
    }

    int ph0 = 0, ph1 = 0;
    for (int s = 0; s < TLEN; s++) {
        const int rb = (s + 1) & 1;        // buffer holding h(s-1)
        const int wb = s & 1;              // buffer receiving h(s)
        if (s > 0) {
            if (rb == 0) { mbar_wait(bar0, ph0);     ph0 ^= 1; if (t == 0) mbar_expect(bar0, 1024); }
            else         { mbar_wait(bar0 + 8, ph1); ph1 ^= 1; if (t == 0) mbar_expect(bar0 + 8, 1024); }
        }

        const int trow = dir ? (TLEN - 1 - s) : s;
        const float xcur = xnext;
        if (q == 0 && s + 1 < TLEN) {
            const int tnext = dir ? (TLEN - 2 - s) : (s + 1);
            xnext = xs[(size_t)tnext * 1024 + G];
        }

        // quarter-partial dot: TWO independent f32x2 chains
        const ulonglong2* hp = reinterpret_cast<const ulonglong2*>(&hsh[rb][q * 68]);
        unsigned long long a0 = 0ull, a1 = 0ull;
#pragma unroll
        for (int i = 0; i < 8; i++) {
            ulonglong2 hv = hp[i];
            fma2(a0, wv[i].x, hv.x);
            fma2(a1, wv[i].y, hv.y);
        }
#pragma unroll
        for (int i = 0; i < 8; i++) {
            ulonglong2 hv = hp[8 + i];
            fma2(a0, wv2[i].x, hv.x);
            fma2(a1, wv2[i].y, hv.y);
        }
        float f0, f1, f2, f3;
        asm("mov.b64 {%0, %1}, %2;" : "=f"(f0), "=f"(f1) : "l"(a0));
        asm("mov.b64 {%0, %1}, %2;" : "=f"(f2), "=f"(f3) : "l"(a1));
        zsh[t] = ((f0 + f1) + (f2 + f3)) + xcur;    // partial; x folded into q==0
        __syncthreads();   // all partials visible; all reads of buffer rb done

        if (t < 32) {      // warp 0: both half-warps compute unit (t&15) gates
            const int u = t & 15;
            const float4 pi = *(const float4*)&zsh[(0 * 16 + u) * 4];
            const float4 pf = *(const float4*)&zsh[(1 * 16 + u) * 4];
            const float4 pg = *(const float4*)&zsh[(2 * 16 + u) * 4];
            const float4 po = *(const float4*)&zsh[(3 * 16 + u) * 4];
            const float zi = (pi.x + pi.y) + (pi.z + pi.w);
            const float zf = (pf.x + pf.y) + (pf.z + pf.w);
            const float zg = (pg.x + pg.y) + (pg.z + pg.w);
            const float zo = (po.x + po.y) + (po.z + po.w);
            const float si = sigm(zi);
            const float sf = sigm(zf);
            const float so = sigm(zo);
            const float c  = sf * creg + si * tanha(zg);
            creg = c;                       // identical on both half-warps
            const float h = so * tanha(c);

            if (s + 1 < TLEN) {
                const uint32_t doff = (uint32_t)wb * 1088u;   // buffer stride 4*68*4 B
                const uint32_t boff = (uint32_t)wb * 8u;
#pragma unroll
                for (int k = 0; k < 8; k++)
                    st_async_f32(rdst[k] + doff, h, rbar[k] + boff);
            }
            if (t < 16)
                hout[(size_t)trow * 512 + dir * 256 + (int)rank * 16 + u] = h;
        }
    }

    // don't exit while peers may still be consuming our last stores
    asm volatile("barrier.cluster.arrive.aligned;" ::: "memory");
    asm volatile("barrier.cluster.wait.aligned;"  ::: "memory");
}

// ---------------- launcher ----------------
extern "C" void kernel_launch(void* const* d_in, const int* in_sizes, int n_in,
                              void* d_out, int out_size)
{
    (void)in_sizes; (void)n_in; (void)out_size;
    const float* x     = (const float*)d_in[0];
    const float* wih0f = (const float*)d_in[1];
    const float* whh0f = (const float*)d_in[2];
    const float* b0f   = (const float*)d_in[3];
    const float* wih0b = (const float*)d_in[4];
    const float* whh0b = (const float*)d_in[5];
    const float* b0b   = (const float*)d_in[6];
    const float* wih1f = (const float*)d_in[7];
    const float* whh1f = (const float*)d_in[8];
    const float* b1f   = (const float*)d_in[9];
    const float* wih1b = (const float*)d_in[10];
    const float* whh1b = (const float*)d_in[11];
    const float* b1b   = (const float*)d_in[12];
    const float* fc1w  = (const float*)d_in[13];
    const float* fc1b  = (const float*)d_in[14];
    const float* fc2w  = (const float*)d_in[15];
    const float* fc2b  = (const float*)d_in[16];
    float* out = (float*)d_out;

    float *xsf, *xsb, *h1, *h2, *z, *e, *nrm;
    cudaGetSymbolAddress((void**)&xsf, g_xsf);
    cudaGetSymbolAddress((void**)&xsb, g_xsb);
    cudaGetSymbolAddress((void**)&h1,  g_h1);
    cudaGetSymbolAddress((void**)&h2,  g_h2);
    cudaGetSymbolAddress((void**)&z,   g_z);
    cudaGetSymbolAddress((void**)&e,   g_e);
    cudaGetSymbolAddress((void**)&nrm, g_nrm);

    // opt in to 16-CTA (non-portable) cluster size
    static int attr_done = 0;
    if (!attr_done) {
        cudaFuncSetAttribute(lstm_scan, cudaFuncAttributeNonPortableClusterSizeAllowed, 1);
        attr_done = 1;
    }

    const dim3 blk(256);

    // layer 0: input projections (M=4096, N=1024, K=128)
    gemm_k<<<dim3(8, 32), blk>>>(x, wih0f, b0f, nullptr, xsf, TLEN, 1024, 128, 0);
    gemm_k<<<dim3(8, 32), blk>>>(x, wih0b, b0b, nullptr, xsb, TLEN, 1024, 128, 0);
    // layer 0 scan
    lstm_scan<<<2 * NCL, SCAN_THREADS>>>(xsf, xsb, whh0f, whh0b, h1);
    // layer 1: input projections (K=512)
    gemm_k<<<dim3(8, 32), blk>>>(h1, wih1f, b1f, nullptr, xsf, TLEN, 1024, 512, 0);
    gemm_k<<<dim3(8, 32), blk>>>(h1, wih1b, b1b, nullptr, xsb, TLEN, 1024, 512, 0);
    // layer 1 scan
    lstm_scan<<<2 * NCL, SCAN_THREADS>>>(xsf, xsb, whh1f, whh1b, h2);
    // fc1 (relu), fc2
    gemm_k<<<dim3(2, 32), blk>>>(h2, fc1w, fc1b, nullptr, z, TLEN, 256, 512, 1);
    gemm_k<<<dim3(2, 32), blk>>>(z,  fc2w, fc2b, nullptr, e, TLEN, 256, 256, 0);
    // reciprocal norms + cosine-distance matrix (multiply-only epilogue)
    norm_k<<<TLEN / 8, 256>>>(e, nrm);
    gemm_k<<<dim3(32, 32), blk>>>(e, e, nullptr, nrm, out, TLEN, TLEN, 256, 2);
}

// round 10
// speedup vs baseline: 1.5273x; 1.0181x over previous
#include <cuda_runtime.h>
#include <cstdint>
#include <math.h>

#define TLEN 4096
#define HDIM 256

// ---------------- scratch (static device arrays; no allocation) ----------------
__device__ float g_xsf[TLEN * 1024];   // 16 MB  input-proj forward (reused per layer)
__device__ float g_xsb[TLEN * 1024];   // 16 MB  input-proj backward
__device__ float g_h1 [TLEN * 512];    // 8 MB   layer0 output [hf | hb]
__device__ float g_h2 [TLEN * 512];    // 8 MB   layer1 output
__device__ float g_z  [TLEN * 256];    // 4 MB   fc1 output
__device__ float g_e  [TLEN * 256];    // 4 MB   fc2 output
__device__ float g_nrm[TLEN];          // reciprocal row norms of e

// ---------------- generic 128x128 SGEMM: C = A(MxK) * B(NxK)^T (+epilogue) ------
// mode 0: C += bias ; mode 1: relu(C + bias) ; mode 2: cosine-distance epilogue
// mode 2 exploits symmetry: blocks with bn<bm exit; off-diagonal tiles are
// mirror-stored so the full matrix is still produced.
__global__ __launch_bounds__(256, 1)
void gemm_k(const float* __restrict__ A, const float* __restrict__ B,
            const float* __restrict__ bias, const float* __restrict__ nrm,
            float* __restrict__ C, int M, int N, int K, int mode)
{
    __shared__ float As[16][128];
    __shared__ float Bs[16][128];

    const int tid = threadIdx.x;
    const int bm = blockIdx.y << 7;
    const int bn = blockIdx.x << 7;
    if (mode == 2 && bn < bm) return;        // symmetric: lower-triangle tiles skip
    const int tx = tid & 15;
    const int ty = tid >> 4;
    const int lr = tid >> 2;
    const int lc = (tid & 3) << 2;

    const float* Ap = A + (size_t)(bm + lr) * K + lc;
    const float* Bp = B + (size_t)(bn + lr) * K + lc;

    float acc[8][8];
#pragma unroll
    for (int i = 0; i < 8; i++)
#pragma unroll
        for (int j = 0; j < 8; j++) acc[i][j] = 0.f;

    for (int k0 = 0; k0 < K; k0 += 16) {
        float4 a0 = *(const float4*)(Ap + k0);
        float4 a1 = *(const float4*)(Ap + (size_t)64 * K + k0);
        float4 b0 = *(const float4*)(Bp + k0);
        float4 b1 = *(const float4*)(Bp + (size_t)64 * K + k0);
        __syncthreads();
        As[lc + 0][lr] = a0.x; As[lc + 1][lr] = a0.y; As[lc + 2][lr] = a0.z; As[lc + 3][lr] = a0.w;
        As[lc + 0][lr + 64] = a1.x; As[lc + 1][lr + 64] = a1.y; As[lc + 2][lr + 64] = a1.z; As[lc + 3][lr + 64] = a1.w;
        Bs[lc + 0][lr] = b0.x; Bs[lc + 1][lr] = b0.y; Bs[lc + 2][lr] = b0.z; Bs[lc + 3][lr] = b0.w;
        Bs[lc + 0][lr + 64] = b1.x; Bs[lc + 1][lr + 64] = b1.y; Bs[lc + 2][lr + 64] = b1.z; Bs[lc + 3][lr + 64] = b1.w;
        __syncthreads();
#pragma unroll
        for (int k = 0; k < 16; k++) {
            float aF[8], bF[8];
            float4 t0 = *(const float4*)&As[k][ty * 8];
            float4 t1 = *(const float4*)&As[k][ty * 8 + 4];
            float4 t2 = *(const float4*)&Bs[k][tx * 8];
            float4 t3 = *(const float4*)&Bs[k][tx * 8 + 4];
            aF[0] = t0.x; aF[1] = t0.y; aF[2] = t0.z; aF[3] = t0.w;
            aF[4] = t1.x; aF[5] = t1.y; aF[6] = t1.z; aF[7] = t1.w;
            bF[0] = t2.x; bF[1] = t2.y; bF[2] = t2.z; bF[3] = t2.w;
            bF[4] = t3.x; bF[5] = t3.y; bF[6] = t3.z; bF[7] = t3.w;
#pragma unroll
            for (int i = 0; i < 8; i++)
#pragma unroll
                for (int j = 0; j < 8; j++)
                    acc[i][j] = fmaf(aF[i], bF[j], acc[i][j]);
        }
    }

    float cj[8];
    if (mode == 2) {
#pragma unroll
        for (int j = 0; j < 8; j++) cj[j] = nrm[bn + tx * 8 + j];   // 1/||col row||
    } else {
#pragma unroll
        for (int j = 0; j < 8; j++) cj[j] = bias[bn + tx * 8 + j];
    }
#pragma unroll
    for (int i = 0; i < 8; i++) {
        const int row = bm + ty * 8 + i;
        float* Crow = C + (size_t)row * N + bn + tx * 8;
        if (mode == 2) {
            const float ri = nrm[row];
#pragma unroll
            for (int j = 0; j < 8; j++) {
                float v = acc[i][j] * ri * cj[j];
                v = fmaxf(v, 1e-6f);
                acc[i][j] = 1.f - v;
            }
        } else {
#pragma unroll
            for (int j = 0; j < 8; j++) {
                float v = acc[i][j] + cj[j];
                if (mode == 1) v = fmaxf(v, 0.f);
                acc[i][j] = v;
            }
        }
        *(float4*)(Crow)     = make_float4(acc[i][0], acc[i][1], acc[i][2], acc[i][3]);
        *(float4*)(Crow + 4) = make_float4(acc[i][4], acc[i][5], acc[i][6], acc[i][7]);
    }
    // mirror store for symmetric mode (off-diagonal tiles)
    if (mode == 2 && bn != bm) {
#pragma unroll
        for (int i = 0; i < 8; i++) {
            const int row = bm + ty * 8 + i;
#pragma unroll
            for (int j = 0; j < 8; j++) {
                const int col = bn + tx * 8 + j;
                C[(size_t)col * N + row] = acc[i][j];
            }
        }
    }
}

// ---------------- row-norm kernel: stores RECIPROCAL norms ----------------
__global__ void norm_k(const float* __restrict__ e, float* __restrict__ nrm)
{
    const int row  = blockIdx.x * 8 + (threadIdx.x >> 5);
    const int lane = threadIdx.x & 31;
    const float* p = e + (size_t)row * 256;
    float s = 0.f;
#pragma unroll
    for (int i = 0; i < 8; i++) { float v = p[lane + i * 32]; s += v * v; }
#pragma unroll
    for (int o = 16; o; o >>= 1) s += __shfl_xor_sync(0xffffffffu, s, o);
    if (lane == 0) nrm[row] = 1.0f / sqrtf(s);
}

// ---------------- LSTM scan helpers ----------------
#define NCL 16
#define SCAN_THREADS 256

__device__ __forceinline__ uint32_t s2u(const void* p)
{
    uint32_t a;
    asm("{ .reg .u64 t; cvta.to.shared.u64 t, %1; cvt.u32.u64 %0, t; }" : "=r"(a) : "l"(p));
    return a;
}
__device__ __forceinline__ uint32_t mapa_u32(uint32_t la, uint32_t rank)
{
    uint32_t ra;
    asm("mapa.shared::cluster.u32 %0, %1, %2;" : "=r"(ra) : "r"(la), "r"(rank));
    return ra;
}
__device__ __forceinline__ void st_async_f32(uint32_t ra_data, float v, uint32_t ra_bar)
{
    asm volatile("st.async.shared::cluster.mbarrier::complete_tx::bytes.u32 [%0], %1, [%2];"
                 :: "r"(ra_data), "r"(__float_as_uint(v)), "r"(ra_bar) : "memory");
}
__device__ __forceinline__ void mbar_init(uint32_t bar, uint32_t cnt)
{
    asm volatile("mbarrier.init.shared.b64 [%0], %1;" :: "r"(bar), "r"(cnt) : "memory");
}
__device__ __forceinline__ void mbar_expect(uint32_t bar, uint32_t bytes)
{
    asm volatile("mbarrier.arrive.expect_tx.shared.b64 _, [%0], %1;" :: "r"(bar), "r"(bytes) : "memory");
}
__device__ __forceinline__ void mbar_wait(uint32_t bar, uint32_t phase)
{
    asm volatile(
        "{\n\t"
        ".reg .pred P%=;\n\t"
        "W%=:\n\t"
        "mbarrier.try_wait.parity.acquire.cta.shared::cta.b64 P%=, [%0], %1, 0x989680;\n\t"
        "@P%= bra.uni D%=;\n\t"
        "bra.uni W%=;\n\t"
        "D%=:\n\t"
        "}"
        :: "r"(bar), "r"(phase) : "memory");
}
__device__ __forceinline__ float tanha(float x)
{
    float y; asm("tanh.approx.f32 %0, %1;" : "=f"(y) : "f"(x)); return y;
}
__device__ __forceinline__ float sigm(float x)
{
    return fmaf(tanha(0.5f * x), 0.5f, 0.5f);
}
__device__ __forceinline__ void fma2(unsigned long long& acc, unsigned long long a, unsigned long long b)
{
    asm("fma.rn.f32x2 %0, %1, %2, %3;" : "=l"(acc) : "l"(a), "l"(b), "l"(acc));
}

// ---------------- LSTM scan: 2 clusters of 16 CTAs (fwd / bwd) ----------------
// R8 proven design: each CTA owns 16 hidden units (64 gate rows), 256 threads
// = 64 rows x 4 quarters. Gate math computed redundantly on both half-warps of
// warp 0 (lane l <-> unit l&15); each lane sends its unit's h to 8 of the 16
// peers. Single full-buffer mbarrier per buffer, expect_tx(1024B).
__global__ void __cluster_dims__(NCL, 1, 1) __launch_bounds__(SCAN_THREADS, 1)
lstm_scan(const float* __restrict__ xsf, const float* __restrict__ xsb,
          const float* __restrict__ whf, const float* __restrict__ whb,
          float* __restrict__ hout)
{
    // padded h layout: 4 segments of 64 floats, stride 68 words -> conflict-free
    __shared__ __align__(16) float hsh[2][4 * 68];
    __shared__ __align__(16) float zsh[SCAN_THREADS];   // partials: [row*4 + q]
    __shared__ __align__(8) unsigned long long mbar[2];

    const int t   = threadIdx.x;
    const int dir = blockIdx.x / NCL;                 // 0 = forward, 1 = backward
    uint32_t rank;
    asm("mov.u32 %0, %%cluster_ctarank;" : "=r"(rank));

    const float* xs  = dir ? xsb : xsf;
    const float* Whh = dir ? whb : whf;

    const int r  = t >> 2;                // gate-row within CTA: 0..63
    const int q  = t & 3;                 // quarter of the dot product
    const int gg = r >> 4;                // gate index 0..3 (i,f,g,o)
    const int uu = r & 15;                // unit within CTA
    const int G  = gg * HDIM + (int)rank * 16 + uu;   // global gate row 0..1023

    // this thread's 64 weights as packed f32x2 pairs (register-resident)
    ulonglong2 wv[8], wv2[8];
    const ulonglong2* wp = reinterpret_cast<const ulonglong2*>(Whh + (size_t)G * HDIM + q * 64);
#pragma unroll
    for (int i = 0; i < 8; i++) wv[i]  = wp[i];
#pragma unroll
    for (int i = 0; i < 8; i++) wv2[i] = wp[8 + i];

    for (int i = t; i < 2 * 4 * 68; i += SCAN_THREADS) ((float*)hsh)[i] = 0.f;

    const uint32_t bar0 = s2u(&mbar[0]);
    if (t == 0) {
        mbar_init(bar0, 1);
        mbar_init(bar0 + 8, 1);
        mbar_expect(bar0, 1024);
        mbar_expect(bar0 + 8, 1024);
    }

    // warp-0 sender constants: lane l owns unit (l&15); sends to 8 dests
    // p = (l>>4)*8 + k. Remote slot of h index rank*16 + (l&15).
    uint32_t rdst[8], rbar[8];
    {
        const int lane = t & 31;
        const int hidx = (int)rank * 16 + (lane & 15);
        const int word = (hidx >> 6) * 68 + (hidx & 63);
        const uint32_t la = s2u(&hsh[0][word]);
        const uint32_t pb = (uint32_t)((lane >> 4) * 8);
#pragma unroll
        for (int k = 0; k < 8; k++) {
            rdst[k] = mapa_u32(la,   pb + k);
            rbar[k] = mapa_u32(bar0, pb + k);
        }
    }

    float creg = 0.f;
    __syncthreads();
    // all CTAs' barriers must be live before any remote st.async
    asm volatile("barrier.cluster.arrive.aligned;" ::: "memory");
    asm volatile("barrier.cluster.wait.aligned;"  ::: "memory");

    // prefetch xs for the first step (q==0 lanes only; folded into partial)
    float xnext = 0.f;
    if (q == 0) {
        const int trow0 = dir ? (TLEN - 1) : 0;
        xnext = xs[(size_t)trow0 * 1024 + G];
    }

    int ph0 = 0, ph1 = 0;
    for (int s = 0; s < TLEN; s++) {
        const int rb = (s + 1) & 1;        // buffer holding h(s-1)
        const int wb = s & 1;              // buffer receiving h(s)
        if (s > 0) {
            if (rb == 0) { mbar_wait(bar0, ph0);     ph0 ^= 1; if (t == 0) mbar_expect(bar0, 1024); }
            else         { mbar_wait(bar0 + 8, ph1); ph1 ^= 1; if (t == 0) mbar_expect(bar0 + 8, 1024); }
        }

        const int trow = dir ? (TLEN - 1 - s) : s;
        const float xcur = xnext;
        if (q == 0 && s + 1 < TLEN) {
            const int tnext = dir ? (TLEN - 2 - s) : (s + 1);
            xnext = xs[(size_t)tnext * 1024 + G];
        }

        // quarter-partial dot: TWO independent f32x2 chains
        const ulonglong2* hp = reinterpret_cast<const ulonglong2*>(&hsh[rb][q * 68]);
        unsigned long long a0 = 0ull, a1 = 0ull;
#pragma unroll
        for (int i = 0; i < 8; i++) {
            ulonglong2 hv = hp[i];
            fma2(a0, wv[i].x, hv.x);
            fma2(a1, wv[i].y, hv.y);
        }
#pragma unroll
        for (int i = 0; i < 8; i++) {
            ulonglong2 hv = hp[8 + i];
            fma2(a0, wv2[i].x, hv.x);
            fma2(a1, wv2[i].y, hv.y);
        }
        float f0, f1, f2, f3;
        asm("mov.b64 {%0, %1}, %2;" : "=f"(f0), "=f"(f1) : "l"(a0));
        asm("mov.b64 {%0, %1}, %2;" : "=f"(f2), "=f"(f3) : "l"(a1));
        zsh[t] = ((f0 + f1) + (f2 + f3)) + xcur;    // partial; x folded into q==0
        __syncthreads();   // all partials visible; all reads of buffer rb done

        if (t < 32) {      // warp 0: both half-warps compute unit (t&15) gates
            const int u = t & 15;
            const float4 pi = *(const float4*)&zsh[(0 * 16 + u) * 4];
            const float4 pf = *(const float4*)&zsh[(1 * 16 + u) * 4];
            const float4 pg = *(const float4*)&zsh[(2 * 16 + u) * 4];
            const float4 po = *(const float4*)&zsh[(3 * 16 + u) * 4];
            const float zi = (pi.x + pi.y) + (pi.z + pi.w);
            const float zf = (pf.x + pf.y) + (pf.z + pf.w);
            const float zg = (pg.x + pg.y) + (pg.z + pg.w);
            const float zo = (po.x + po.y) + (po.z + po.w);
            const float si = sigm(zi);
            const float sf = sigm(zf);
            const float so = sigm(zo);
            const float c  = sf * creg + si * tanha(zg);
            creg = c;                       // identical on both half-warps
            const float h = so * tanha(c);

            if (s + 1 < TLEN) {
                const uint32_t doff = (uint32_t)wb * 1088u;   // buffer stride 4*68*4 B
                const uint32_t boff = (uint32_t)wb * 8u;
#pragma unroll
                for (int k = 0; k < 8; k++)
                    st_async_f32(rdst[k] + doff, h, rbar[k] + boff);
            }
            if (t < 16)
                hout[(size_t)trow * 512 + dir * 256 + (int)rank * 16 + u] = h;
        }
    }

    // don't exit while peers may still be consuming our last stores
    asm volatile("barrier.cluster.arrive.aligned;" ::: "memory");
    asm volatile("barrier.cluster.wait.aligned;"  ::: "memory");
}

// ---------------- launcher ----------------
extern "C" void kernel_launch(void* const* d_in, const int* in_sizes, int n_in,
                              void* d_out, int out_size)
{
    (void)in_sizes; (void)n_in; (void)out_size;
    const float* x     = (const float*)d_in[0];
    const float* wih0f = (const float*)d_in[1];
    const float* whh0f = (const float*)d_in[2];
    const float* b0f   = (const float*)d_in[3];
    const float* wih0b = (const float*)d_in[4];
    const float* whh0b = (const float*)d_in[5];
    const float* b0b   = (const float*)d_in[6];
    const float* wih1f = (const float*)d_in[7];
    const float* whh1f = (const float*)d_in[8];
    const float* b1f   = (const float*)d_in[9];
    const float* wih1b = (const float*)d_in[10];
    const float* whh1b = (const float*)d_in[11];
    const float* b1b   = (const float*)d_in[12];
    const float* fc1w  = (const float*)d_in[13];
    const float* fc1b  = (const float*)d_in[14];
    const float* fc2w  = (const float*)d_in[15];
    const float* fc2b  = (const float*)d_in[16];
    float* out = (float*)d_out;

    float *xsf, *xsb, *h1, *h2, *z, *e, *nrm;
    cudaGetSymbolAddress((void**)&xsf, g_xsf);
    cudaGetSymbolAddress((void**)&xsb, g_xsb);
    cudaGetSymbolAddress((void**)&h1,  g_h1);
    cudaGetSymbolAddress((void**)&h2,  g_h2);
    cudaGetSymbolAddress((void**)&z,   g_z);
    cudaGetSymbolAddress((void**)&e,   g_e);
    cudaGetSymbolAddress((void**)&nrm, g_nrm);

    // opt in to 16-CTA (non-portable) cluster size
    static int attr_done = 0;
    if (!attr_done) {
        cudaFuncSetAttribute(lstm_scan, cudaFuncAttributeNonPortableClusterSizeAllowed, 1);
        attr_done = 1;
    }

    const dim3 blk(256);

    // layer 0: input projections (M=4096, N=1024, K=128)
    gemm_k<<<dim3(8, 32), blk>>>(x, wih0f, b0f, nullptr, xsf, TLEN, 1024, 128, 0);
    gemm_k<<<dim3(8, 32), blk>>>(x, wih0b, b0b, nullptr, xsb, TLEN, 1024, 128, 0);
    // layer 0 scan
    lstm_scan<<<2 * NCL, SCAN_THREADS>>>(xsf, xsb, whh0f, whh0b, h1);
    // layer 1: input projections (K=512)
    gemm_k<<<dim3(8, 32), blk>>>(h1, wih1f, b1f, nullptr, xsf, TLEN, 1024, 512, 0);
    gemm_k<<<dim3(8, 32), blk>>>(h1, wih1b, b1b, nullptr, xsb, TLEN, 1024, 512, 0);
    // layer 1 scan
    lstm_scan<<<2 * NCL, SCAN_THREADS>>>(xsf, xsb, whh1f, whh1b, h2);
    // fc1 (relu), fc2
    gemm_k<<<dim3(2, 32), blk>>>(h2, fc1w, fc1b, nullptr, z, TLEN, 256, 512, 1);
    gemm_k<<<dim3(2, 32), blk>>>(z,  fc2w, fc2b, nullptr, e, TLEN, 256, 256, 0);
    // reciprocal norms + symmetric cosine-distance matrix (upper tiles + mirror)
    norm_k<<<TLEN / 8, 256>>>(e, nrm);
    gemm_k<<<dim3(32, 32), blk>>>(e, e, nullptr, nrm, out, TLEN, TLEN, 256, 2);
}